// round 12
// baseline (speedup 1.0000x reference)
#include <cuda_runtime.h>
#include <math.h>
#include <stdint.h>

#define NRTOK 16384
#define NTOK  32768      // B*Nr
#define MM    64
#define AD    128
#define HIDN  512
#define TT    64         // tokens per CTA tile
#define HC    64         // hidden chunk
#define SCALE 0.17677669529663687f  // 1/sqrt(32)

#define YS_STR 132       // Ys  [tok][k]  stride (words): 132 % 32 == 4 -> A-frag conflict-free
#define W1_STR 72        // W1s [k][j]    stride: 72  % 32 == 8 -> B-frag conflict-free
#define W2_STR 136       // W2s [j][a]    stride: 136 % 32 == 8 -> B-frag conflict-free
#define HS_STR 68        // Hs  [tok][j]  stride: 68  % 32 == 4 -> A-frag conflict-free

// smem map (bytes):
//   [0, 33792)        Ys : u32[64*132]   tf32 y tile [tok][k] (persists through MLP)
//   [33792, 70656)    Ws : u32           W1 chunk [128][64] s72  OR  W2 chunk [64][128] s136
//   [70656, 88064)    union (17408B): attention scratch | Hs u32[64*68]
#define SM_W_OFF 33792
#define SM_U_OFF 70656
#define SMEM_BYTES 88064

// attention scratch offsets (in floats) within union area (4352 floats)
#define O_LS   0        // Ls[256]   logits [slot][head]
#define O_AS   256      // As[256]   probs  [slot][head]
#define O_VP   512      // Vp[1024]  V partials [warp][a]
#define O_QS   1536     // Qs[128]
#define O_CNT  1664     // CntS[64] (ints)
#define O_RSA  1728     // RsA[4][8] reduction slots
#define O_IDX8 1760     // Idx8T[64*64] (uint8, transposed) -> floats 1760..2784

__device__ __forceinline__ uint32_t cvt_tf32(float x) {
    uint32_t r; asm("cvt.rna.tf32.f32 %0, %1;" : "=r"(r) : "f"(x)); return r;
}
__device__ __forceinline__ void mma_tf32(float* d, uint32_t a0, uint32_t a1,
                                         uint32_t a2, uint32_t a3,
                                         uint32_t b0, uint32_t b1) {
    asm("mma.sync.aligned.m16n8k8.row.col.f32.tf32.tf32.f32 "
        "{%0,%1,%2,%3}, {%4,%5,%6,%7}, {%8,%9}, {%0,%1,%2,%3};"
        : "+f"(d[0]), "+f"(d[1]), "+f"(d[2]), "+f"(d[3])
        : "r"(a0), "r"(a1), "r"(a2), "r"(a3), "r"(b0), "r"(b1));
}

// scratch: x = post-LN1 (residual base for final add)
__device__ float g_x[NTOK * AD];

__global__ __launch_bounds__(256, 2)
void bev_fused_kernel(const float* __restrict__ Q, const float* __restrict__ K,
                      const float* __restrict__ V, const int* __restrict__ mask,
                      const float* __restrict__ ln1g, const float* __restrict__ ln1b,
                      const float* __restrict__ ln2g, const float* __restrict__ ln2b,
                      const float* __restrict__ W1, const float* __restrict__ b1,
                      const float* __restrict__ W2, const float* __restrict__ b2,
                      float* __restrict__ Out)
{
    extern __shared__ char smem_raw[];
    uint32_t* Ys = reinterpret_cast<uint32_t*>(smem_raw);
    uint32_t* Ws = reinterpret_cast<uint32_t*>(smem_raw + SM_W_OFF);
    uint32_t* Hs = reinterpret_cast<uint32_t*>(smem_raw + SM_U_OFF);
    float*    AT = reinterpret_cast<float*>(smem_raw + SM_U_OFF);
    float*    Ls   = AT + O_LS;
    float*    As   = AT + O_AS;
    float*    Vp   = AT + O_VP;
    float*    Qs   = AT + O_QS;
    int*      CntS = reinterpret_cast<int*>(AT + O_CNT);
    float*    RsA  = AT + O_RSA;
    unsigned char* Idx8 = reinterpret_cast<unsigned char*>(AT + O_IDX8);

    const int tid  = threadIdx.x;
    const int lane = tid & 31;
    const int wid  = tid >> 5;
    const size_t T0 = (size_t)blockIdx.x * TT;

    // per-thread LN params (a == tid for tid<128)
    float l1gv = 0.f, l1bv = 0.f, l2gv = 0.f, l2bv = 0.f;
    if (tid < AD) {
        l1gv = ln1g[tid]; l1bv = ln1b[tid];
        l2gv = ln2g[tid]; l2bv = ln2b[tid];
    }

    const int hq = lane >> 3;   // head owned by this lane's 8-group (a = 4*lane)

    // ======= prologue A: compaction for ALL 64 tokens (warp w -> tokens w, w+8, ...) =======
    // transposed store: slot s -> byte (s&7)*8 + (s>>3), so warp w reads one u64 at w*8
#pragma unroll
    for (int j = 0; j < 8; j++) {
        const int tl = wid + (j << 3);
        const size_t t = T0 + tl;
        const int* mrow = mask + ((t & (NRTOK - 1)) << 6);
        int mv0 = mrow[lane];
        int mv1 = mrow[lane + 32];
        unsigned bb0 = __ballot_sync(0xffffffffu, mv0 == 0);
        unsigned bb1 = __ballot_sync(0xffffffffu, mv1 == 0);
        int c0 = __popc(bb0);
        if ((bb0 >> lane) & 1) {
            int s = __popc(bb0 & ((1u << lane) - 1u));
            Idx8[(tl << 6) + ((s & 7) << 3) + (s >> 3)] = (unsigned char)lane;
        }
        if ((bb1 >> lane) & 1) {
            int s = c0 + __popc(bb1 & ((1u << lane) - 1u));
            Idx8[(tl << 6) + ((s & 7) << 3) + (s >> 3)] = (unsigned char)(32 + lane);
        }
        if (lane == 0) CntS[tl] = c0 + __popc(bb1);
    }

    // ======= prologue B: LN1-param constant sums (threads 0..127) =======
    if (tid < AD) {
        float c1 = l1gv, c2 = l1gv * l1gv, c3 = l1gv * l1bv, c4 = l1bv, c5 = l1bv * l1bv;
#pragma unroll
        for (int s = 16; s >= 1; s >>= 1) {
            c1 += __shfl_xor_sync(0xffffffffu, c1, s);
            c2 += __shfl_xor_sync(0xffffffffu, c2, s);
            c3 += __shfl_xor_sync(0xffffffffu, c3, s);
            c4 += __shfl_xor_sync(0xffffffffu, c4, s);
            c5 += __shfl_xor_sync(0xffffffffu, c5, s);
        }
        if (lane == 0) {
            RsA[(wid << 3) + 0] = c1; RsA[(wid << 3) + 1] = c2;
            RsA[(wid << 3) + 2] = c3; RsA[(wid << 3) + 3] = c4;
            RsA[(wid << 3) + 4] = c5;
        }
    }
    __syncthreads();                                   // Idx8/CntS/RsA ready

    float Cg = 0.f, Cg2 = 0.f, Cgb = 0.f, Cb = 0.f, Cb2 = 0.f;
    if (tid < AD) {
        Cg  = RsA[0] + RsA[8] + RsA[16] + RsA[24];
        Cg2 = RsA[1] + RsA[9] + RsA[17] + RsA[25];
        Cgb = RsA[2] + RsA[10] + RsA[18] + RsA[26];
        Cb  = RsA[3] + RsA[11] + RsA[19] + RsA[27];
        Cb2 = RsA[4] + RsA[12] + RsA[20] + RsA[28];
    }

    // ======= pipeline prologue: K rows + Q for token 0 =======
    int cnt_cur = CntS[0];
    float4 q4 = *reinterpret_cast<const float4*>(&Q[T0 * AD + (lane << 2)]);
    uint64_t ki = *reinterpret_cast<const uint64_t*>(&Idx8[wid << 3]);
    float4 kv[8];
#pragma unroll
    for (int k = 0; k < 8; k++) {
        int s = wid + (k << 3);
        bool act = s < cnt_cur;
        int m = (int)((ki >> (k << 3)) & 0xff);
        kv[k] = act ? *reinterpret_cast<const float4*>(&K[(T0 * MM + m) * AD + (lane << 2)])
                    : make_float4(0.f, 0.f, 0.f, 0.f);
    }

    // =========================== phase 1: attention + LN1 + LN2 ===========================
    for (int tl = 0; tl < TT; tl++) {
        const size_t t = T0 + tl;

        // ---- issue V loads for current token (consumed after softmax) ----
        uint64_t vi = *reinterpret_cast<const uint64_t*>(&Idx8[(tl << 6) + (wid << 3)]);
        float4 vv[8];
#pragma unroll
        for (int k = 0; k < 8; k++) {
            int s = wid + (k << 3);
            bool act = s < cnt_cur;
            int m = (int)((vi >> (k << 3)) & 0xff);
            vv[k] = act ? *reinterpret_cast<const float4*>(&V[(t * MM + m) * AD + (lane << 2)])
                        : make_float4(0.f, 0.f, 0.f, 0.f);
        }

        if (wid == 0) *reinterpret_cast<float4*>(&Qs[lane << 2]) = q4;

        // ---- consume kv: dots -> Ls ----
#pragma unroll
        for (int k = 0; k < 8; k++) {
            int s = wid + (k << 3);
            if (s < cnt_cur) {
                float part = q4.x * kv[k].x + q4.y * kv[k].y + q4.z * kv[k].z + q4.w * kv[k].w;
                part += __shfl_xor_sync(0xffffffffu, part, 1);
                part += __shfl_xor_sync(0xffffffffu, part, 2);
                part += __shfl_xor_sync(0xffffffffu, part, 4);
                if ((lane & 7) == 0) Ls[(s << 2) + hq] = part * SCALE;
            }
        }

        // ---- prefetch next token's K rows + Q (covered by softmax/LN below) ----
        int cnt_nxt = 0;
        float4 q4n = make_float4(0.f, 0.f, 0.f, 0.f);
        if (tl < TT - 1) {
            cnt_nxt = CntS[tl + 1];
            q4n = *reinterpret_cast<const float4*>(&Q[(t + 1) * AD + (lane << 2)]);
        }
        uint64_t kin = *reinterpret_cast<const uint64_t*>(&Idx8[((tl + 1) << 6) + (wid << 3)]);
        float4 kvn[8];
#pragma unroll
        for (int k = 0; k < 8; k++) {
            int s = wid + (k << 3);
            bool act = s < cnt_nxt;
            int m = (int)((kin >> (k << 3)) & 0xff);
            kvn[k] = act ? *reinterpret_cast<const float4*>(&K[((t + 1) * MM + m) * AD + (lane << 2)])
                         : make_float4(0.f, 0.f, 0.f, 0.f);
        }

        __syncthreads();                               // B2: Ls ready

        // ---- softmax over compacted set (no max-sub: logits bounded): warp w<4 = head w ----
        if (wid < 4) {
            float e0 = (lane      < cnt_cur) ? __expf(Ls[(lane << 2) + wid])        : 0.f;
            float e1 = (lane + 32 < cnt_cur) ? __expf(Ls[((lane + 32) << 2) + wid]) : 0.f;
            float ss = e0 + e1;
#pragma unroll
            for (int s = 16; s >= 1; s >>= 1)
                ss += __shfl_xor_sync(0xffffffffu, ss, s);
            float inv = 1.0f / ss;
            if (lane      < cnt_cur) As[(lane << 2) + wid]        = e0 * inv;
            if (lane + 32 < cnt_cur) As[((lane + 32) << 2) + wid] = e1 * inv;
        }
        __syncthreads();                               // B3: As ready

        // ---- consume vv with weights ----
        {
            float4 acc = make_float4(0.f, 0.f, 0.f, 0.f);
#pragma unroll
            for (int k = 0; k < 8; k++) {
                int s = wid + (k << 3);
                if (s < cnt_cur) {
                    float w = As[(s << 2) + hq];
                    acc.x += w * vv[k].x; acc.y += w * vv[k].y;
                    acc.z += w * vv[k].z; acc.w += w * vv[k].w;
                }
            }
            *reinterpret_cast<float4*>(&Vp[(wid << 7) + (lane << 2)]) = acc;
        }
        __syncthreads();                               // B4: Vp ready

        // ---- single-pass LN1+LN2 statistics (6 parallel chains) ----
        float x = 0.0f;
        if (tid < AD) {
            float o = 0.0f;
#pragma unroll
            for (int w = 0; w < 8; w++) o += Vp[(w << 7) + tid];
            x = Qs[tid] + o;
            float xg = x * l1gv;
            float s1 = x, s2 = x * x, s3 = xg, s4 = xg * l1gv, s5 = xg * xg, s6 = xg * l1bv;
#pragma unroll
            for (int s = 16; s >= 1; s >>= 1) {
                s1 += __shfl_xor_sync(0xffffffffu, s1, s);
                s2 += __shfl_xor_sync(0xffffffffu, s2, s);
                s3 += __shfl_xor_sync(0xffffffffu, s3, s);
                s4 += __shfl_xor_sync(0xffffffffu, s4, s);
                s5 += __shfl_xor_sync(0xffffffffu, s5, s);
                s6 += __shfl_xor_sync(0xffffffffu, s6, s);
            }
            if (lane == 0) {
                RsA[(wid << 3) + 0] = s1; RsA[(wid << 3) + 1] = s2;
                RsA[(wid << 3) + 2] = s3; RsA[(wid << 3) + 3] = s4;
                RsA[(wid << 3) + 4] = s5; RsA[(wid << 3) + 5] = s6;
            }
        }
        __syncthreads();                               // B5: stats ready
        if (tid < AD) {
            float S1 = RsA[0] + RsA[8] + RsA[16] + RsA[24];
            float S2 = RsA[1] + RsA[9] + RsA[17] + RsA[25];
            float S3 = RsA[2] + RsA[10] + RsA[18] + RsA[26];
            float S4 = RsA[3] + RsA[11] + RsA[19] + RsA[27];
            float S5 = RsA[4] + RsA[12] + RsA[20] + RsA[28];
            float S6 = RsA[5] + RsA[13] + RsA[21] + RsA[29];
            const float inv128 = 1.0f / AD;
            float mu  = S1 * inv128;
            float var = S2 * inv128 - mu * mu;
            float r   = rsqrtf(var + 1e-5f);
            float xn  = (x - mu) * r * l1gv + l1bv;
            float mu2 = (r * (S3 - mu * Cg) + Cb) * inv128;
            float m2  = (r * r * (S5 - 2.f * mu * S4 + mu * mu * Cg2)
                         + 2.f * r * (S6 - mu * Cgb) + Cb2) * inv128;
            float var2 = m2 - mu2 * mu2;
            float r2   = rsqrtf(var2 + 1e-5f);
            float y = (xn - mu2) * r2 * l2gv + l2bv;
            g_x[t * AD + tid] = xn;
            Ys[tl * YS_STR + tid] = cvt_tf32(y);       // y tile, tf32, [tok][k]
        }

        // ---- rotate pipeline ----
        cnt_cur = cnt_nxt;
        q4 = q4n;
#pragma unroll
        for (int k = 0; k < 8; k++) kv[k] = kvn[k];
    }

    // =========================== phase 2: MLP via tf32 tensor cores ===========================
    // warp w: M-tile tm = w&3 (tokens tbase..tbase+15), N-half nh = w>>2
    const int tm    = wid & 3;
    const int nh    = wid >> 2;
    const int tbase = tm << 4;
    const int gid   = lane >> 2;     // 0..7
    const int tig   = lane & 3;      // 0..3

    float acc2[8][4];                // GEMM2 accum: 8 n8-tiles over cols nh*64..+63
#pragma unroll
    for (int i = 0; i < 8; i++)
#pragma unroll
        for (int k = 0; k < 4; k++) acc2[i][k] = 0.0f;

    for (int c = 0; c < HIDN / HC; c++) {
        __syncthreads();   // W/Hs free; also attn->MLP transition on first iter

        // ---- stage W1 chunk [128 k][64 j] -> tf32, stride 72 ----
        const float* W1c = W1 + c * HC;
#pragma unroll
        for (int i = 0; i < 8; i++) {
            int e  = tid + 256 * i;              // 2048 float4
            int k  = e >> 4;
            int j4 = (e & 15) << 2;
            float4 v = *reinterpret_cast<const float4*>(&W1c[(size_t)k * HIDN + j4]);
            uint4 tv = make_uint4(cvt_tf32(v.x), cvt_tf32(v.y), cvt_tf32(v.z), cvt_tf32(v.w));
            *reinterpret_cast<uint4*>(&Ws[k * W1_STR + j4]) = tv;
        }
        __syncthreads();

        // ---- GEMM1: H[64 tok][64 hid] = Ys @ W1chunk (16 k8-steps) ----
        float acc1[4][4];
#pragma unroll
        for (int i = 0; i < 4; i++)
#pragma unroll
            for (int k = 0; k < 4; k++) acc1[i][k] = 0.0f;

#pragma unroll 4
        for (int kk = 0; kk < 16; kk++) {
            const int k0 = kk << 3;
            uint32_t a0 = Ys[(tbase + gid)     * YS_STR + k0 + tig];
            uint32_t a1 = Ys[(tbase + gid + 8) * YS_STR + k0 + tig];
            uint32_t a2 = Ys[(tbase + gid)     * YS_STR + k0 + tig + 4];
            uint32_t a3 = Ys[(tbase + gid + 8) * YS_STR + k0 + tig + 4];
#pragma unroll
            for (int nt = 0; nt < 4; nt++) {
                const int jc = (nh << 5) + (nt << 3) + gid;
                uint32_t b0 = Ws[(k0 + tig)     * W1_STR + jc];
                uint32_t b1 = Ws[(k0 + tig + 4) * W1_STR + jc];
                mma_tf32(acc1[nt], a0, a1, a2, a3, b0, b1);
            }
        }

        // ---- bias + exact gelu -> Hs (tf32 pairs) ----
#pragma unroll
        for (int nt = 0; nt < 4; nt++) {
            const int j = (nh << 5) + (nt << 3) + (tig << 1);
            float bja = __ldg(&b1[c * HC + j]);
            float bjb = __ldg(&b1[c * HC + j + 1]);
            float h00 = acc1[nt][0] + bja, h01 = acc1[nt][1] + bjb;
            float h10 = acc1[nt][2] + bja, h11 = acc1[nt][3] + bjb;
            float g00 = 0.5f * h00 * (1.0f + erff(h00 * 0.70710678118654752f));
            float g01 = 0.5f * h01 * (1.0f + erff(h01 * 0.70710678118654752f));
            float g10 = 0.5f * h10 * (1.0f + erff(h10 * 0.70710678118654752f));
            float g11 = 0.5f * h11 * (1.0f + erff(h11 * 0.70710678118654752f));
            *reinterpret_cast<uint2*>(&Hs[(tbase + gid)     * HS_STR + j]) =
                make_uint2(cvt_tf32(g00), cvt_tf32(g01));
            *reinterpret_cast<uint2*>(&Hs[(tbase + gid + 8) * HS_STR + j]) =
                make_uint2(cvt_tf32(g10), cvt_tf32(g11));
        }
        __syncthreads();   // W free (GEMM1 done), Hs ready

        // ---- stage W2 chunk [64 j][128 a] -> tf32, stride 136 ----
        const float* W2c = W2 + (size_t)(c * HC) * AD;
#pragma unroll
        for (int i = 0; i < 8; i++) {
            int e  = tid + 256 * i;              // 2048 float4
            int j  = e >> 5;
            int a4 = (e & 31) << 2;
            float4 v = *reinterpret_cast<const float4*>(&W2c[(size_t)j * AD + a4]);
            uint4 tv = make_uint4(cvt_tf32(v.x), cvt_tf32(v.y), cvt_tf32(v.z), cvt_tf32(v.w));
            *reinterpret_cast<uint4*>(&Ws[j * W2_STR + a4]) = tv;
        }
        __syncthreads();

        // ---- GEMM2: acc2 += Hchunk @ W2chunk (8 k8-steps) ----
#pragma unroll 4
        for (int kk = 0; kk < 8; kk++) {
            const int j0 = kk << 3;
            uint32_t a0 = Hs[(tbase + gid)     * HS_STR + j0 + tig];
            uint32_t a1 = Hs[(tbase + gid + 8) * HS_STR + j0 + tig];
            uint32_t a2 = Hs[(tbase + gid)     * HS_STR + j0 + tig + 4];
            uint32_t a3 = Hs[(tbase + gid + 8) * HS_STR + j0 + tig + 4];
#pragma unroll
            for (int nt = 0; nt < 8; nt++) {
                const int ac = (nh << 6) + (nt << 3) + gid;
                uint32_t b0 = Ws[(j0 + tig)     * W2_STR + ac];
                uint32_t b1 = Ws[(j0 + tig + 4) * W2_STR + ac];
                mma_tf32(acc2[nt], a0, a1, a2, a3, b0, b1);
            }
        }
    }

    // ---- epilogue: out = x + acc2 + b2 (float2 per d-pair) ----
#pragma unroll
    for (int nt = 0; nt < 8; nt++) {
        const int av = (nh << 6) + (nt << 3) + (tig << 1);
        float b2a = __ldg(&b2[av]);
        float b2b = __ldg(&b2[av + 1]);
        size_t r0 = (T0 + tbase + gid) * (size_t)AD + av;
        size_t r1 = (T0 + tbase + gid + 8) * (size_t)AD + av;
        float2 x0 = *reinterpret_cast<const float2*>(&g_x[r0]);
        float2 x1 = *reinterpret_cast<const float2*>(&g_x[r1]);
        float2 o0 = make_float2(x0.x + acc2[nt][0] + b2a, x0.y + acc2[nt][1] + b2b);
        float2 o1 = make_float2(x1.x + acc2[nt][2] + b2a, x1.y + acc2[nt][3] + b2b);
        *reinterpret_cast<float2*>(&Out[r0]) = o0;
        *reinterpret_cast<float2*>(&Out[r1]) = o1;
    }
}

// ===========================================================================
extern "C" void kernel_launch(void* const* d_in, const int* in_sizes, int n_in,
                              void* d_out, int out_size)
{
    const float* Q    = (const float*)d_in[0];
    const float* K    = (const float*)d_in[1];
    const float* V    = (const float*)d_in[2];
    const int*   mask = (const int*)  d_in[3];
    const float* ln1g = (const float*)d_in[4];
    const float* ln1b = (const float*)d_in[5];
    const float* ln2g = (const float*)d_in[6];
    const float* ln2b = (const float*)d_in[7];
    const float* W1   = (const float*)d_in[8];
    const float* b1   = (const float*)d_in[9];
    const float* W2   = (const float*)d_in[10];
    const float* b2   = (const float*)d_in[11];
    float* Out = (float*)d_out;

    static bool attr_set = false;
    if (!attr_set) {
        cudaFuncSetAttribute(bev_fused_kernel,
                             cudaFuncAttributeMaxDynamicSharedMemorySize,
                             SMEM_BYTES);
        attr_set = true;
    }

    bev_fused_kernel<<<NTOK / TT, 256, SMEM_BYTES>>>(
        Q, K, V, mask, ln1g, ln1b, ln2g, ln2b, W1, b1, W2, b2, Out);
}

// round 16
// speedup vs baseline: 1.1442x; 1.1442x over previous
#include <cuda_runtime.h>
#include <math.h>
#include <stdint.h>

#define NRTOK 16384
#define NTOK  32768      // B*Nr
#define MM    64
#define AD    128
#define HIDN  512
#define TT    64         // tokens per MLP CTA tile
#define HC    64         // hidden chunk
#define SCALE 0.17677669529663687f  // 1/sqrt(32)

#define YS_STR 132       // Ys  [tok][k]  stride (words): 132 % 32 == 4 -> A-frag conflict-free
#define W1_STR 72        // W1s [k][j]    stride: 72  % 32 == 8 -> B-frag conflict-free
#define W2_STR 136       // W2s [j][a]    stride: 136 % 32 == 8 -> B-frag conflict-free
#define HS_STR 68        // Hs  [tok][j]  stride: 68  % 32 == 4 -> A-frag conflict-free

// MLP kernel smem map (bytes):
//   [0, 33792)        Ys : u32[64*132]
//   [33792, 70656)    Ws : u32   W1 chunk [128][64] s72  OR  W2 chunk [64][128] s136
//   [70656, 88064)    Hs : u32[64*68]
#define SM_W_OFF 33792
#define SM_U_OFF 70656
#define SMEM_BYTES 88064

__device__ __forceinline__ uint32_t cvt_tf32(float x) {
    uint32_t r; asm("cvt.rna.tf32.f32 %0, %1;" : "=r"(r) : "f"(x)); return r;
}
__device__ __forceinline__ void mma_tf32(float* d, uint32_t a0, uint32_t a1,
                                         uint32_t a2, uint32_t a3,
                                         uint32_t b0, uint32_t b1) {
    asm("mma.sync.aligned.m16n8k8.row.col.f32.tf32.tf32.f32 "
        "{%0,%1,%2,%3}, {%4,%5,%6,%7}, {%8,%9}, {%0,%1,%2,%3};"
        : "+f"(d[0]), "+f"(d[1]), "+f"(d[2]), "+f"(d[3])
        : "r"(a0), "r"(a1), "r"(a2), "r"(a3), "r"(b0), "r"(b1));
}

// scratch: x = post-LN1 (residual base), y = post-LN2 (MLP input)
__device__ float g_x[NTOK * AD];
__device__ float g_y[NTOK * AD];

// ===========================================================================
// Kernel A: per-token masked attention + residual + LN1 + LN2
// grid = 32768 (1 token/CTA), 256 threads, small smem -> high occupancy
// ===========================================================================
__global__ __launch_bounds__(256)
void bev_attn_kernel(const float* __restrict__ Q, const float* __restrict__ K,
                     const float* __restrict__ V, const int* __restrict__ mask,
                     const float* __restrict__ ln1g, const float* __restrict__ ln1b,
                     const float* __restrict__ ln2g, const float* __restrict__ ln2b)
{
    __shared__ float Ls[256];    // logits [slot][head]
    __shared__ float As[256];    // probs  [slot][head]
    __shared__ float Vp[1024];   // V partials [warp][a]
    __shared__ float Qs[128];
    __shared__ int   IdxS[64];
    __shared__ float2 Rs[4], Rs2[4];

    const int tid  = threadIdx.x;
    const int lane = tid & 31;
    const int wid  = tid >> 5;
    const size_t t = blockIdx.x;
    const int hq = lane >> 3;        // head for this lane's quad (a = 4*lane)

    // ---- mask ballot + compaction ----
    const int* mrow = mask + ((t & (NRTOK - 1)) << 6);
    int mv0 = mrow[lane];
    int mv1 = mrow[lane + 32];
    unsigned b0 = __ballot_sync(0xffffffffu, mv0 == 0);
    unsigned b1 = __ballot_sync(0xffffffffu, mv1 == 0);
    int cnt0 = __popc(b0);
    int cnt  = cnt0 + __popc(b1);
    if (wid == 0 && ((b0 >> lane) & 1))
        IdxS[__popc(b0 & ((1u << lane) - 1u))] = lane;
    if (wid == 1 && ((b1 >> lane) & 1))
        IdxS[cnt0 + __popc(b1 & ((1u << lane) - 1u))] = 32 + lane;

    const float4 q4 = *reinterpret_cast<const float4*>(&Q[t * AD + (lane << 2)]);
    if (wid == 0) *reinterpret_cast<float4*>(&Qs[lane << 2]) = q4;

    __syncthreads();                               // B1: IdxS/Qs ready

    // ---- K burst (predicated, 8 rows/warp) + dots ----
    int ms[8];
#pragma unroll
    for (int k = 0; k < 8; k++) {
        int s = wid + (k << 3);
        ms[k] = (s < cnt) ? IdxS[s] : -1;
    }
    float4 kv[8];
#pragma unroll
    for (int k = 0; k < 8; k++) {
        kv[k] = (ms[k] >= 0)
              ? *reinterpret_cast<const float4*>(&K[(t * MM + ms[k]) * AD + (lane << 2)])
              : make_float4(0.f, 0.f, 0.f, 0.f);
    }
#pragma unroll
    for (int k = 0; k < 8; k++) {
        if (ms[k] >= 0) {
            float part = q4.x * kv[k].x + q4.y * kv[k].y + q4.z * kv[k].z + q4.w * kv[k].w;
            part += __shfl_xor_sync(0xffffffffu, part, 1);
            part += __shfl_xor_sync(0xffffffffu, part, 2);
            part += __shfl_xor_sync(0xffffffffu, part, 4);
            if ((lane & 7) == 0) Ls[((wid + (k << 3)) << 2) + hq] = part * SCALE;
        }
    }

    // ---- V burst issued now (consumed after softmax; latency hidden) ----
    float4 vv[8];
#pragma unroll
    for (int k = 0; k < 8; k++) {
        vv[k] = (ms[k] >= 0)
              ? *reinterpret_cast<const float4*>(&V[(t * MM + ms[k]) * AD + (lane << 2)])
              : make_float4(0.f, 0.f, 0.f, 0.f);
    }

    __syncthreads();                               // B2: Ls ready

    // ---- softmax over compacted set: warp w<4 handles head w ----
    if (wid < 4) {
        float l0 = (lane      < cnt) ? Ls[(lane << 2) + wid]        : -1e30f;
        float l1 = (lane + 32 < cnt) ? Ls[((lane + 32) << 2) + wid] : -1e30f;
        float mx = fmaxf(l0, l1);
#pragma unroll
        for (int s = 16; s >= 1; s >>= 1)
            mx = fmaxf(mx, __shfl_xor_sync(0xffffffffu, mx, s));
        float e0 = __expf(l0 - mx), e1 = __expf(l1 - mx);
        float ss = e0 + e1;
#pragma unroll
        for (int s = 16; s >= 1; s >>= 1)
            ss += __shfl_xor_sync(0xffffffffu, ss, s);
        float inv = 1.0f / ss;
        if (lane      < cnt) As[(lane << 2) + wid]        = e0 * inv;
        if (lane + 32 < cnt) As[((lane + 32) << 2) + wid] = e1 * inv;
    }
    __syncthreads();                               // B3: As ready

    // ---- weighted V sum ----
    {
        float4 acc = make_float4(0.f, 0.f, 0.f, 0.f);
#pragma unroll
        for (int k = 0; k < 8; k++) {
            if (ms[k] >= 0) {
                float w = As[((wid + (k << 3)) << 2) + hq];
                acc.x += w * vv[k].x; acc.y += w * vv[k].y;
                acc.z += w * vv[k].z; acc.w += w * vv[k].w;
            }
        }
        *reinterpret_cast<float4*>(&Vp[(wid << 7) + (lane << 2)]) = acc;
    }
    __syncthreads();                               // B4: Vp ready

    // ---- reduce + residual + LN1 + LN2 (threads 0..127, a = tid) ----
    float x = 0.0f, xn = 0.0f;
    if (tid < AD) {
        float o = 0.0f;
#pragma unroll
        for (int w = 0; w < 8; w++) o += Vp[(w << 7) + tid];
        x = Qs[tid] + o;
        float sx = x, sxx = x * x;
#pragma unroll
        for (int s = 16; s >= 1; s >>= 1) {
            sx  += __shfl_xor_sync(0xffffffffu, sx,  s);
            sxx += __shfl_xor_sync(0xffffffffu, sxx, s);
        }
        if (lane == 0) Rs[wid] = make_float2(sx, sxx);
    }
    __syncthreads();                               // B5
    if (tid < AD) {
        float tsum = Rs[0].x + Rs[1].x + Rs[2].x + Rs[3].x;
        float tsq  = Rs[0].y + Rs[1].y + Rs[2].y + Rs[3].y;
        float mu   = tsum * (1.0f / AD);
        float var  = tsq * (1.0f / AD) - mu * mu;
        float rstd = rsqrtf(var + 1e-5f);
        xn = (x - mu) * rstd * ln1g[tid] + ln1b[tid];
        float sx = xn, sxx = xn * xn;
#pragma unroll
        for (int s = 16; s >= 1; s >>= 1) {
            sx  += __shfl_xor_sync(0xffffffffu, sx,  s);
            sxx += __shfl_xor_sync(0xffffffffu, sxx, s);
        }
        if (lane == 0) Rs2[wid] = make_float2(sx, sxx);
    }
    __syncthreads();                               // B6
    if (tid < AD) {
        float tsum = Rs2[0].x + Rs2[1].x + Rs2[2].x + Rs2[3].x;
        float tsq  = Rs2[0].y + Rs2[1].y + Rs2[2].y + Rs2[3].y;
        float mu2   = tsum * (1.0f / AD);
        float var2  = tsq * (1.0f / AD) - mu2 * mu2;
        float rstd2 = rsqrtf(var2 + 1e-5f);
        float y = (xn - mu2) * rstd2 * ln2g[tid] + ln2b[tid];
        g_x[t * AD + tid] = xn;
        g_y[t * AD + tid] = y;
    }
}

// ===========================================================================
// Kernel B: MLP via tf32 tensor cores (R11 phase-2, staging y from gmem)
// grid = 512 (64 tokens/CTA), 256 threads
// ===========================================================================
__global__ __launch_bounds__(256, 2)
void bev_mlp_kernel(const float* __restrict__ W1, const float* __restrict__ b1,
                    const float* __restrict__ W2, const float* __restrict__ b2,
                    float* __restrict__ Out)
{
    extern __shared__ char smem_raw[];
    uint32_t* Ys = reinterpret_cast<uint32_t*>(smem_raw);
    uint32_t* Ws = reinterpret_cast<uint32_t*>(smem_raw + SM_W_OFF);
    uint32_t* Hs = reinterpret_cast<uint32_t*>(smem_raw + SM_U_OFF);

    const int tid  = threadIdx.x;
    const int lane = tid & 31;
    const int wid  = tid >> 5;
    const size_t T0 = (size_t)blockIdx.x * TT;

    // ---- stage y tile -> tf32 smem [tok][k], stride 132 ----
#pragma unroll
    for (int i = 0; i < 8; i++) {
        int e  = tid + 256 * i;              // 2048 float4
        int tt = e >> 5;
        int k4 = (e & 31) << 2;
        float4 v = *reinterpret_cast<const float4*>(&g_y[(T0 + tt) * AD + k4]);
        uint4 tv = make_uint4(cvt_tf32(v.x), cvt_tf32(v.y), cvt_tf32(v.z), cvt_tf32(v.w));
        *reinterpret_cast<uint4*>(&Ys[tt * YS_STR + k4]) = tv;
    }

    // warp w: M-tile tm = w&3 (tokens tbase..tbase+15), N-half nh = w>>2
    const int tm    = wid & 3;
    const int nh    = wid >> 2;
    const int tbase = tm << 4;
    const int gid   = lane >> 2;     // 0..7
    const int tig   = lane & 3;      // 0..3

    float acc2[8][4];
#pragma unroll
    for (int i = 0; i < 8; i++)
#pragma unroll
        for (int k = 0; k < 4; k++) acc2[i][k] = 0.0f;

    for (int c = 0; c < HIDN / HC; c++) {
        __syncthreads();   // Ys staged (first iter) / W,Hs free (later iters)

        // ---- stage W1 chunk [128 k][64 j] -> tf32, stride 72 ----
        const float* W1c = W1 + c * HC;
#pragma unroll
        for (int i = 0; i < 8; i++) {
            int e  = tid + 256 * i;
            int k  = e >> 4;
            int j4 = (e & 15) << 2;
            float4 v = *reinterpret_cast<const float4*>(&W1c[(size_t)k * HIDN + j4]);
            uint4 tv = make_uint4(cvt_tf32(v.x), cvt_tf32(v.y), cvt_tf32(v.z), cvt_tf32(v.w));
            *reinterpret_cast<uint4*>(&Ws[k * W1_STR + j4]) = tv;
        }
        __syncthreads();

        // ---- GEMM1: H[64 tok][64 hid] = Ys @ W1chunk ----
        float acc1[4][4];
#pragma unroll
        for (int i = 0; i < 4; i++)
#pragma unroll
            for (int k = 0; k < 4; k++) acc1[i][k] = 0.0f;

#pragma unroll 4
        for (int kk = 0; kk < 16; kk++) {
            const int k0 = kk << 3;
            uint32_t a0 = Ys[(tbase + gid)     * YS_STR + k0 + tig];
            uint32_t a1 = Ys[(tbase + gid + 8) * YS_STR + k0 + tig];
            uint32_t a2 = Ys[(tbase + gid)     * YS_STR + k0 + tig + 4];
            uint32_t a3 = Ys[(tbase + gid + 8) * YS_STR + k0 + tig + 4];
#pragma unroll
            for (int nt = 0; nt < 4; nt++) {
                const int jc = (nh << 5) + (nt << 3) + gid;
                uint32_t bb0 = Ws[(k0 + tig)     * W1_STR + jc];
                uint32_t bb1 = Ws[(k0 + tig + 4) * W1_STR + jc];
                mma_tf32(acc1[nt], a0, a1, a2, a3, bb0, bb1);
            }
        }

        // ---- bias + exact gelu -> Hs ----
#pragma unroll
        for (int nt = 0; nt < 4; nt++) {
            const int j = (nh << 5) + (nt << 3) + (tig << 1);
            float bja = __ldg(&b1[c * HC + j]);
            float bjb = __ldg(&b1[c * HC + j + 1]);
            float h00 = acc1[nt][0] + bja, h01 = acc1[nt][1] + bjb;
            float h10 = acc1[nt][2] + bja, h11 = acc1[nt][3] + bjb;
            float g00 = 0.5f * h00 * (1.0f + erff(h00 * 0.70710678118654752f));
            float g01 = 0.5f * h01 * (1.0f + erff(h01 * 0.70710678118654752f));
            float g10 = 0.5f * h10 * (1.0f + erff(h10 * 0.70710678118654752f));
            float g11 = 0.5f * h11 * (1.0f + erff(h11 * 0.70710678118654752f));
            *reinterpret_cast<uint2*>(&Hs[(tbase + gid)     * HS_STR + j]) =
                make_uint2(cvt_tf32(g00), cvt_tf32(g01));
            *reinterpret_cast<uint2*>(&Hs[(tbase + gid + 8) * HS_STR + j]) =
                make_uint2(cvt_tf32(g10), cvt_tf32(g11));
        }
        __syncthreads();

        // ---- stage W2 chunk [64 j][128 a] -> tf32, stride 136 ----
        const float* W2c = W2 + (size_t)(c * HC) * AD;
#pragma unroll
        for (int i = 0; i < 8; i++) {
            int e  = tid + 256 * i;
            int j  = e >> 5;
            int a4 = (e & 31) << 2;
            float4 v = *reinterpret_cast<const float4*>(&W2c[(size_t)j * AD + a4]);
            uint4 tv = make_uint4(cvt_tf32(v.x), cvt_tf32(v.y), cvt_tf32(v.z), cvt_tf32(v.w));
            *reinterpret_cast<uint4*>(&Ws[j * W2_STR + a4]) = tv;
        }
        __syncthreads();

        // ---- GEMM2: acc2 += Hchunk @ W2chunk ----
#pragma unroll 4
        for (int kk = 0; kk < 8; kk++) {
            const int j0 = kk << 3;
            uint32_t a0 = Hs[(tbase + gid)     * HS_STR + j0 + tig];
            uint32_t a1 = Hs[(tbase + gid + 8) * HS_STR + j0 + tig];
            uint32_t a2 = Hs[(tbase + gid)     * HS_STR + j0 + tig + 4];
            uint32_t a3 = Hs[(tbase + gid + 8) * HS_STR + j0 + tig + 4];
#pragma unroll
            for (int nt = 0; nt < 8; nt++) {
                const int ac = (nh << 6) + (nt << 3) + gid;
                uint32_t bb0 = Ws[(j0 + tig)     * W2_STR + ac];
                uint32_t bb1 = Ws[(j0 + tig + 4) * W2_STR + ac];
                mma_tf32(acc2[nt], a0, a1, a2, a3, bb0, bb1);
            }
        }
    }

    // ---- epilogue: out = x + acc2 + b2 ----
#pragma unroll
    for (int nt = 0; nt < 8; nt++) {
        const int av = (nh << 6) + (nt << 3) + (tig << 1);
        float b2a = __ldg(&b2[av]);
        float b2b = __ldg(&b2[av + 1]);
        size_t r0 = (T0 + tbase + gid) * (size_t)AD + av;
        size_t r1 = (T0 + tbase + gid + 8) * (size_t)AD + av;
        float2 x0 = *reinterpret_cast<const float2*>(&g_x[r0]);
        float2 x1 = *reinterpret_cast<const float2*>(&g_x[r1]);
        float2 o0 = make_float2(x0.x + acc2[nt][0] + b2a, x0.y + acc2[nt][1] + b2b);
        float2 o1 = make_float2(x1.x + acc2[nt][2] + b2a, x1.y + acc2[nt][3] + b2b);
        *reinterpret_cast<float2*>(&Out[r0]) = o0;
        *reinterpret_cast<float2*>(&Out[r1]) = o1;
    }
}

// ===========================================================================
extern "C" void kernel_launch(void* const* d_in, const int* in_sizes, int n_in,
                              void* d_out, int out_size)
{
    const float* Q    = (const float*)d_in[0];
    const float* K    = (const float*)d_in[1];
    const float* V    = (const float*)d_in[2];
    const int*   mask = (const int*)  d_in[3];
    const float* ln1g = (const float*)d_in[4];
    const float* ln1b = (const float*)d_in[5];
    const float* ln2g = (const float*)d_in[6];
    const float* ln2b = (const float*)d_in[7];
    const float* W1   = (const float*)d_in[8];
    const float* b1   = (const float*)d_in[9];
    const float* W2   = (const float*)d_in[10];
    const float* b2   = (const float*)d_in[11];
    float* Out = (float*)d_out;

    static bool attr_set = false;
    if (!attr_set) {
        cudaFuncSetAttribute(bev_mlp_kernel,
                             cudaFuncAttributeMaxDynamicSharedMemorySize,
                             SMEM_BYTES);
        attr_set = true;
    }

    bev_attn_kernel<<<NTOK, 256>>>(Q, K, V, mask, ln1g, ln1b, ln2g, ln2b);
    bev_mlp_kernel<<<NTOK / TT, 256, SMEM_BYTES>>>(W1, b1, W2, b2, Out);
}